// round 7
// baseline (speedup 1.0000x reference)
#include <cuda_runtime.h>
#include <cstdint>

#define NPTS 100000
#define CDIM 128
#define HDIM 64
#define NK   27
#define GP   128
#define NT_GM ((NPTS + GP - 1) / GP)          // 782 (gemm tiles)
#define TP    128
#define NT_MM ((NPTS + TP - 1) / TP)          // 782 (sconv tiles)

// Scratch (allocation-free rule: __device__ globals)
__device__ float g_convx[NPTS * HDIM];
__device__ float g_trans[NPTS * HDIM];
__device__ float g_r1[NPTS * HDIM];
__device__ float g_r2[NPTS * HDIM];
__device__ float g_zero[64];                  // zeroed each launch (memset)

__device__ __forceinline__ uint32_t tf32_rna(float x) {
    uint32_t r;
    asm("cvt.rna.tf32.f32 %0, %1;" : "=r"(r) : "f"(x));
    return r;
}
__device__ __forceinline__ uint4 tf32x4(float4 v) {
    uint4 o;
    o.x = tf32_rna(v.x); o.y = tf32_rna(v.y);
    o.z = tf32_rna(v.z); o.w = tf32_rna(v.w);
    return o;
}
__device__ __forceinline__ void mma_tf32(float* c, const uint32_t* a, const uint32_t* b) {
    asm volatile(
        "mma.sync.aligned.m16n8k8.row.col.f32.tf32.tf32.f32 "
        "{%0,%1,%2,%3}, {%4,%5,%6,%7}, {%8,%9}, {%0,%1,%2,%3};"
        : "+f"(c[0]), "+f"(c[1]), "+f"(c[2]), "+f"(c[3])
        : "r"(a[0]), "r"(a[1]), "r"(a[2]), "r"(a[3]), "r"(b[0]), "r"(b[1]));
}
__device__ __forceinline__ uint32_t smem_u32(const void* p) {
    uint32_t a;
    asm("{ .reg .u64 t; cvta.to.shared.u64 t, %1; cvt.u32.u64 %0, t; }" : "=r"(a) : "l"(p));
    return a;
}
__device__ __forceinline__ void cp16(uint32_t dst, const void* src) {
    asm volatile("cp.async.ca.shared.global [%0], [%1], 16;" :: "r"(dst), "l"(src));
}
#define CP_COMMIT() asm volatile("cp.async.commit_group;" ::: "memory")
#define CP_WAIT(n)  asm volatile("cp.async.wait_group %0;" :: "n"(n) : "memory")

// ---------------------------------------------------------------------------
// gemm mma smem: X[128][132] | W[2][32][132]    (tf32 bit patterns)
#define GXSTR 132
#define GX_OFF 0
#define GW_OFF (GP * GXSTR * 4)                  // 67584
#define GWSTR 132
#define GW_BUF (32 * GWSTR * 4)                  // 16896
#define G_SMEM (GW_OFF + 2 * GW_BUF)             // 101376

// sconv mma smem: G[2][128][68] | W[2][64][72]  (raw f32 bits)
#define MM_GSTR 68
#define MM_GBUF (128 * MM_GSTR * 4)              // 34816
#define MM_G_OFF 0
#define MM_W_OFF (2 * MM_GBUF)                   // 69632
#define MM_WSTR 72
#define MM_WBUF (64 * MM_WSTR * 4)               // 18432
#define MM_SMEM (MM_W_OFF + 2 * MM_WBUF)         // 106496

// ---------------------------------------------------------------------------
// K1: y = x @ w1 + b1 ; split -> g_convx (d<64) / g_trans (d>=64).  tf32 mma.
// ---------------------------------------------------------------------------
__global__ __launch_bounds__(256, 2) void gemm1_kernel(const float* __restrict__ x,
                                                       const float* __restrict__ w1,
                                                       const float* __restrict__ b1)
{
    extern __shared__ char sm[];
    uint32_t* s_x = (uint32_t*)(sm + GX_OFF);
    uint32_t* s_wb[2] = { (uint32_t*)(sm + GW_OFF), (uint32_t*)(sm + GW_OFF + GW_BUF) };

    const int tid  = threadIdx.x;
    const int wid  = tid >> 5;
    const int lane = tid & 31;
    const int mw   = wid >> 1;
    const int nw   = wid & 1;
    const int g    = lane >> 2;
    const int tg   = lane & 3;
    const int p0   = blockIdx.x * GP;

#pragma unroll
    for (int j = 0; j < 16; j++) {
        int f = tid + j * 256;
        int row = f >> 5, c4 = f & 31;
        int r = p0 + row;
        float4 v = (r < NPTS) ? *(const float4*)&x[r * CDIM + c4 * 4]
                              : make_float4(0.f, 0.f, 0.f, 0.f);
        *(uint4*)&s_x[row * GXSTR + c4 * 4] = tf32x4(v);
    }
    uint4 wv[4];
#pragma unroll
    for (int j = 0; j < 4; j++) wv[j] = tf32x4(((const float4*)w1)[tid + j * 256]);

    float acc[2][8][4];
#pragma unroll
    for (int mt = 0; mt < 2; mt++)
#pragma unroll
        for (int nt = 0; nt < 8; nt++)
#pragma unroll
            for (int i = 0; i < 4; i++) acc[mt][nt][i] = 0.f;

    for (int ch = 0; ch < 4; ch++) {
        const int b = ch & 1;
#pragma unroll
        for (int j = 0; j < 4; j++) {
            int f = tid + j * 256;
            *(uint4*)&s_wb[b][(f >> 5) * GWSTR + (f & 31) * 4] = wv[j];
        }
        __syncthreads();
        if (ch < 3) {
            const float4* ws = (const float4*)&w1[(ch + 1) * 32 * CDIM];
#pragma unroll
            for (int j = 0; j < 4; j++) wv[j] = tf32x4(ws[tid + j * 256]);
        }
        const uint32_t* ga = s_x + (mw * 32 + g) * GXSTR + ch * 32 + tg;
        const uint32_t* wb = s_wb[b] + tg * GWSTR + nw * 64 + g;
#pragma unroll
        for (int kk = 0; kk < 4; kk++) {
            const int co = kk * 8;
            uint32_t a[2][4];
#pragma unroll
            for (int mt = 0; mt < 2; mt++) {
                const uint32_t* gr = ga + mt * 16 * GXSTR + co;
                a[mt][0] = gr[0];
                a[mt][1] = gr[8 * GXSTR];
                a[mt][2] = gr[4];
                a[mt][3] = gr[8 * GXSTR + 4];
            }
            uint32_t bf[8][2];
#pragma unroll
            for (int nt = 0; nt < 8; nt++) {
                const uint32_t* wr = wb + co * GWSTR + nt * 8;
                bf[nt][0] = wr[0];
                bf[nt][1] = wr[4 * GWSTR];
            }
#pragma unroll
            for (int mt = 0; mt < 2; mt++)
#pragma unroll
                for (int nt = 0; nt < 8; nt++)
                    mma_tf32(acc[mt][nt], a[mt], bf[nt]);
        }
    }

#pragma unroll
    for (int mt = 0; mt < 2; mt++) {
#pragma unroll
        for (int h = 0; h < 2; h++) {
            int row = p0 + mw * 32 + mt * 16 + g + h * 8;
            if (row < NPTS) {
#pragma unroll
                for (int nt = 0; nt < 8; nt++) {
                    int d = nw * 64 + nt * 8 + 2 * tg;
                    float2 bb = *(const float2*)&b1[d];
                    float2 o;
                    o.x = acc[mt][nt][h * 2 + 0] + bb.x;
                    o.y = acc[mt][nt][h * 2 + 1] + bb.y;
                    if (nw == 0)
                        *(float2*)&g_convx[row * HDIM + d] = o;
                    else
                        *(float2*)&g_trans[row * HDIM + d - HDIM] = o;
                }
            }
        }
    }
}

// ---------------------------------------------------------------------------
// K2/K3: sconv3 + ReLU via mma.sync tf32, cp.async staging (no cvt, no STS).
// ---------------------------------------------------------------------------
__global__ __launch_bounds__(256, 2) void sconv_mma_kernel(const float* __restrict__ feat,
                                                           float* __restrict__ outp,
                                                           const float* __restrict__ rw,
                                                           const float* __restrict__ rb,
                                                           const int* __restrict__ nbr)
{
    extern __shared__ char sm[];
    const uint32_t smb = smem_u32(sm);
    const uint32_t gB[2] = { smb + MM_G_OFF, smb + MM_G_OFF + MM_GBUF };
    const uint32_t wB[2] = { smb + MM_W_OFF, smb + MM_W_OFF + MM_WBUF };
    uint32_t* s_gb[2] = { (uint32_t*)(sm + MM_G_OFF), (uint32_t*)(sm + MM_G_OFF + MM_GBUF) };
    uint32_t* s_wb[2] = { (uint32_t*)(sm + MM_W_OFF), (uint32_t*)(sm + MM_W_OFF + MM_WBUF) };

    const int tid  = threadIdx.x;
    const int wid  = tid >> 5;
    const int lane = tid & 31;
    const int mw   = wid >> 1;
    const int nw   = wid & 1;
    const int g    = lane >> 2;
    const int tg   = lane & 3;
    const int p0   = blockIdx.x * TP;

    // gather role: 2 threads per point, each half (32 floats = 128B)
    const int pl = tid >> 1;
    const int hf = tid & 1;
    const int pt_g = p0 + pl;
    const bool pt_ok = (pt_g < NPTS);
    const uint32_t g_dst_off = (uint32_t)(pl * MM_GSTR + hf * 32) * 4;
    // W staging: 4 chunks of 16B per thread
    uint32_t w_dst_off[4];
    const float* w_src_base[4];
#pragma unroll
    for (int j = 0; j < 4; j++) {
        int f = tid + j * 256;
        w_dst_off[j] = (uint32_t)((f >> 4) * MM_WSTR + (f & 15) * 4) * 4;
        w_src_base[j] = rw + f * 4;
    }

    // source row for offset k (zero row if invalid)
    auto gsrc = [&](int idx) -> const float* {
        return (idx >= 0) ? (feat + (long)idx * HDIM + hf * 32) : (g_zero + hf * 32);
    };
    auto issue = [&](int k, int b, int idx) {
        const float* s = gsrc(idx);
        uint32_t gd = gB[b] + g_dst_off;
#pragma unroll
        for (int j = 0; j < 8; j++) cp16(gd + j * 16, s + j * 4);
        const float* wsk = rw + k * HDIM * HDIM;
#pragma unroll
        for (int j = 0; j < 4; j++) cp16(wB[b] + w_dst_off[j], w_src_base[j] + k * HDIM * HDIM);
        (void)wsk;
    };

    // prologue: k=0, k=1 in flight; idx for k=2 prefetched
    int idx0 = pt_ok ? nbr[pt_g] : -1;
    int idx1 = pt_ok ? nbr[NPTS + pt_g] : -1;
    issue(0, 0, idx0); CP_COMMIT();
    issue(1, 1, idx1); CP_COMMIT();
    int idx_n = (pt_ok && 2 < NK) ? nbr[2 * NPTS + pt_g] : -1;

    float acc[2][4][4];
#pragma unroll
    for (int mt = 0; mt < 2; mt++)
#pragma unroll
        for (int nt = 0; nt < 4; nt++)
#pragma unroll
            for (int i = 0; i < 4; i++) acc[mt][nt][i] = 0.f;

    for (int k = 0; k < NK; k++) {
        const int b = k & 1;
        if (k == NK - 1) CP_WAIT(0); else CP_WAIT(1);
        __syncthreads();                       // all threads' k-loads visible

        // compute: 8 K-steps of m16n8k8 from buffer b
        const uint32_t* ga = s_gb[b] + (mw * 32 + g) * MM_GSTR + tg;
        const uint32_t* wb = s_wb[b] + tg * MM_WSTR + nw * 32 + g;
#pragma unroll
        for (int kk = 0; kk < 8; kk++) {
            const int co = kk * 8;
            uint32_t a[2][4];
#pragma unroll
            for (int mt = 0; mt < 2; mt++) {
                const uint32_t* gr = ga + mt * 16 * MM_GSTR + co;
                a[mt][0] = gr[0];
                a[mt][1] = gr[8 * MM_GSTR];
                a[mt][2] = gr[4];
                a[mt][3] = gr[8 * MM_GSTR + 4];
            }
            uint32_t bf[4][2];
#pragma unroll
            for (int nt = 0; nt < 4; nt++) {
                const uint32_t* wr = wb + co * MM_WSTR + nt * 8;
                bf[nt][0] = wr[0];
                bf[nt][1] = wr[4 * MM_WSTR];
            }
#pragma unroll
            for (int mt = 0; mt < 2; mt++)
#pragma unroll
                for (int nt = 0; nt < 4; nt++)
                    mma_tf32(acc[mt][nt], a[mt], bf[nt]);
        }

        __syncthreads();                       // buffer b free
        if (k + 2 < NK) {
            issue(k + 2, b, idx_n); CP_COMMIT();
            idx_n = (pt_ok && k + 3 < NK) ? nbr[(k + 3) * NPTS + pt_g] : -1;
        }
    }

    // epilogue: bias + ReLU + store
#pragma unroll
    for (int mt = 0; mt < 2; mt++) {
#pragma unroll
        for (int half = 0; half < 2; half++) {
            int pt = p0 + mw * 32 + mt * 16 + g + half * 8;
            if (pt < NPTS) {
                float* orow = outp + (long)pt * HDIM;
#pragma unroll
                for (int nt = 0; nt < 4; nt++) {
                    int d = nw * 32 + nt * 8 + 2 * tg;
                    float2 bb = *(const float2*)&rb[d];
                    float2 o;
                    o.x = fmaxf(acc[mt][nt][half * 2 + 0] + bb.x, 0.f);
                    o.y = fmaxf(acc[mt][nt][half * 2 + 1] + bb.y, 0.f);
                    *(float2*)&orow[d] = o;
                }
            }
        }
    }
}

// ---------------------------------------------------------------------------
// K4: out = x + concat(g_r2 + 2*g_convx, g_trans) @ w2 + b2.  tf32 mma.
// ---------------------------------------------------------------------------
__global__ __launch_bounds__(256, 2) void gemm2_kernel(const float* __restrict__ x,
                                                       const float* __restrict__ w2,
                                                       const float* __restrict__ b2,
                                                       float* __restrict__ out)
{
    extern __shared__ char sm[];
    uint32_t* s_x = (uint32_t*)(sm + GX_OFF);
    uint32_t* s_wb[2] = { (uint32_t*)(sm + GW_OFF), (uint32_t*)(sm + GW_OFF + GW_BUF) };

    const int tid  = threadIdx.x;
    const int wid  = tid >> 5;
    const int lane = tid & 31;
    const int mw   = wid >> 1;
    const int nw   = wid & 1;
    const int g    = lane >> 2;
    const int tg   = lane & 3;
    const int p0   = blockIdx.x * GP;

#pragma unroll
    for (int j = 0; j < 16; j++) {
        int f = tid + j * 256;
        int row = f >> 5, c4 = f & 31;
        int r = p0 + row;
        float4 v = make_float4(0.f, 0.f, 0.f, 0.f);
        if (r < NPTS) {
            if (c4 < 16) {
                float4 a = *(const float4*)&g_r2[r * HDIM + c4 * 4];
                float4 b = *(const float4*)&g_convx[r * HDIM + c4 * 4];
                v = make_float4(fmaf(2.f, b.x, a.x), fmaf(2.f, b.y, a.y),
                                fmaf(2.f, b.z, a.z), fmaf(2.f, b.w, a.w));
            } else {
                v = *(const float4*)&g_trans[r * HDIM + (c4 - 16) * 4];
            }
        }
        *(uint4*)&s_x[row * GXSTR + c4 * 4] = tf32x4(v);
    }
    uint4 wv[4];
#pragma unroll
    for (int j = 0; j < 4; j++) wv[j] = tf32x4(((const float4*)w2)[tid + j * 256]);

    float acc[2][8][4];
#pragma unroll
    for (int mt = 0; mt < 2; mt++)
#pragma unroll
        for (int nt = 0; nt < 8; nt++)
#pragma unroll
            for (int i = 0; i < 4; i++) acc[mt][nt][i] = 0.f;

    for (int ch = 0; ch < 4; ch++) {
        const int b = ch & 1;
#pragma unroll
        for (int j = 0; j < 4; j++) {
            int f = tid + j * 256;
            *(uint4*)&s_wb[b][(f >> 5) * GWSTR + (f & 31) * 4] = wv[j];
        }
        __syncthreads();
        if (ch < 3) {
            const float4* ws = (const float4*)&w2[(ch + 1) * 32 * CDIM];
#pragma unroll
            for (int j = 0; j < 4; j++) wv[j] = tf32x4(ws[tid + j * 256]);
        }
        const uint32_t* ga = s_x + (mw * 32 + g) * GXSTR + ch * 32 + tg;
        const uint32_t* wb = s_wb[b] + tg * GWSTR + nw * 64 + g;
#pragma unroll
        for (int kk = 0; kk < 4; kk++) {
            const int co = kk * 8;
            uint32_t a[2][4];
#pragma unroll
            for (int mt = 0; mt < 2; mt++) {
                const uint32_t* gr = ga + mt * 16 * GXSTR + co;
                a[mt][0] = gr[0];
                a[mt][1] = gr[8 * GXSTR];
                a[mt][2] = gr[4];
                a[mt][3] = gr[8 * GXSTR + 4];
            }
            uint32_t bf[8][2];
#pragma unroll
            for (int nt = 0; nt < 8; nt++) {
                const uint32_t* wr = wb + co * GWSTR + nt * 8;
                bf[nt][0] = wr[0];
                bf[nt][1] = wr[4 * GWSTR];
            }
#pragma unroll
            for (int mt = 0; mt < 2; mt++)
#pragma unroll
                for (int nt = 0; nt < 8; nt++)
                    mma_tf32(acc[mt][nt], a[mt], bf[nt]);
        }
    }

#pragma unroll
    for (int mt = 0; mt < 2; mt++) {
#pragma unroll
        for (int h = 0; h < 2; h++) {
            int row = p0 + mw * 32 + mt * 16 + g + h * 8;
            if (row < NPTS) {
#pragma unroll
                for (int nt = 0; nt < 8; nt++) {
                    int d = nw * 64 + nt * 8 + 2 * tg;
                    float2 bb = *(const float2*)&b2[d];
                    float2 xv = *(const float2*)&x[row * CDIM + d];
                    float2 o;
                    o.x = acc[mt][nt][h * 2 + 0] + bb.x + xv.x;
                    o.y = acc[mt][nt][h * 2 + 1] + bb.y + xv.y;
                    *(float2*)&out[row * CDIM + d] = o;
                }
            }
        }
    }
}

// ---------------------------------------------------------------------------
extern "C" void kernel_launch(void* const* d_in, const int* in_sizes, int n_in,
                              void* d_out, int out_size)
{
    const float* x   = (const float*)d_in[0];
    const float* w1  = (const float*)d_in[1];
    const float* b1  = (const float*)d_in[2];
    const float* w2  = (const float*)d_in[3];
    const float* b2  = (const float*)d_in[4];
    const float* rw1 = (const float*)d_in[5];
    const float* rb1 = (const float*)d_in[6];
    const float* rw2 = (const float*)d_in[7];
    const float* rb2 = (const float*)d_in[8];
    const int*   nbr = (const int*)d_in[9];
    float* out = (float*)d_out;

    float* p_convx; cudaGetSymbolAddress((void**)&p_convx, g_convx);
    float* p_r1;    cudaGetSymbolAddress((void**)&p_r1,    g_r1);
    float* p_r2;    cudaGetSymbolAddress((void**)&p_r2,    g_r2);
    float* p_zero;  cudaGetSymbolAddress((void**)&p_zero,  g_zero);

    cudaFuncSetAttribute(gemm1_kernel,     cudaFuncAttributeMaxDynamicSharedMemorySize, G_SMEM);
    cudaFuncSetAttribute(sconv_mma_kernel, cudaFuncAttributeMaxDynamicSharedMemorySize, MM_SMEM);
    cudaFuncSetAttribute(gemm2_kernel,     cudaFuncAttributeMaxDynamicSharedMemorySize, G_SMEM);

    cudaMemsetAsync(p_zero, 0, 64 * sizeof(float));
    gemm1_kernel<<<NT_GM, 256, G_SMEM>>>(x, w1, b1);
    sconv_mma_kernel<<<NT_MM, 256, MM_SMEM>>>(p_convx, p_r1, rw1, rb1, nbr);
    sconv_mma_kernel<<<NT_MM, 256, MM_SMEM>>>(p_r1,    p_r2, rw2, rb2, nbr);
    gemm2_kernel<<<NT_GM, 256, G_SMEM>>>(x, w2, b2, out);
}

// round 8
// speedup vs baseline: 1.0982x; 1.0982x over previous
#include <cuda_runtime.h>
#include <cstdint>

#define NPTS 100000
#define CDIM 128
#define HDIM 64
#define NK   27
#define GP   128
#define NT_GM ((NPTS + GP - 1) / GP)          // 782 (gemm tiles)
#define TP    128
#define NT_MM ((NPTS + TP - 1) / TP)          // 782 (sconv tiles)

// Scratch (allocation-free rule: __device__ globals)
__device__ float g_convx[NPTS * HDIM];
__device__ float g_trans[NPTS * HDIM];
__device__ float g_r1[NPTS * HDIM];
__device__ float g_r2[NPTS * HDIM];
__device__ float g_zero[64];                  // zeroed each launch (memset)

__device__ __forceinline__ uint32_t tf32_rna(float x) {
    uint32_t r;
    asm("cvt.rna.tf32.f32 %0, %1;" : "=r"(r) : "f"(x));
    return r;
}
__device__ __forceinline__ uint4 tf32x4(float4 v) {
    uint4 o;
    o.x = tf32_rna(v.x); o.y = tf32_rna(v.y);
    o.z = tf32_rna(v.z); o.w = tf32_rna(v.w);
    return o;
}
__device__ __forceinline__ void mma_tf32(float* c, const uint32_t* a, const uint32_t* b) {
    asm volatile(
        "mma.sync.aligned.m16n8k8.row.col.f32.tf32.tf32.f32 "
        "{%0,%1,%2,%3}, {%4,%5,%6,%7}, {%8,%9}, {%0,%1,%2,%3};"
        : "+f"(c[0]), "+f"(c[1]), "+f"(c[2]), "+f"(c[3])
        : "r"(a[0]), "r"(a[1]), "r"(a[2]), "r"(a[3]), "r"(b[0]), "r"(b[1]));
}
__device__ __forceinline__ uint32_t smem_u32(const void* p) {
    uint32_t a;
    asm("{ .reg .u64 t; cvta.to.shared.u64 t, %1; cvt.u32.u64 %0, t; }" : "=r"(a) : "l"(p));
    return a;
}
__device__ __forceinline__ void cp16(uint32_t dst, const void* src) {
    asm volatile("cp.async.ca.shared.global [%0], [%1], 16;" :: "r"(dst), "l"(src));
}
#define CP_COMMIT() asm volatile("cp.async.commit_group;" ::: "memory")
#define CP_WAIT(n)  asm volatile("cp.async.wait_group %0;" :: "n"(n) : "memory")

// ---------------------------------------------------------------------------
// gemm mma smem: X[128][132] | W[2][32][132]    (tf32 bit patterns)
#define GXSTR 132
#define GX_OFF 0
#define GW_OFF (GP * GXSTR * 4)                  // 67584
#define GWSTR 132
#define GW_BUF (32 * GWSTR * 4)                  // 16896
#define G_SMEM (GW_OFF + 2 * GW_BUF)             // 101376

// sconv smem: 3 G stages (swizzled [128][64] f32, 32KB each) + 1 W buf (16KB)
#define MM_GSTAGE 32768
#define MM_W_OFF  (3 * MM_GSTAGE)                // 98304
#define MM_SMEM   (MM_W_OFF + 16384)             // 114688

// ---------------------------------------------------------------------------
// K1: y = x @ w1 + b1 ; split -> g_convx (d<64) / g_trans (d>=64).  tf32 mma.
// ---------------------------------------------------------------------------
__global__ __launch_bounds__(256, 2) void gemm1_kernel(const float* __restrict__ x,
                                                       const float* __restrict__ w1,
                                                       const float* __restrict__ b1)
{
    extern __shared__ char sm[];
    uint32_t* s_x = (uint32_t*)(sm + GX_OFF);
    uint32_t* s_wb[2] = { (uint32_t*)(sm + GW_OFF), (uint32_t*)(sm + GW_OFF + GW_BUF) };

    const int tid  = threadIdx.x;
    const int wid  = tid >> 5;
    const int lane = tid & 31;
    const int mw   = wid >> 1;
    const int nw   = wid & 1;
    const int g    = lane >> 2;
    const int tg   = lane & 3;
    const int p0   = blockIdx.x * GP;

#pragma unroll
    for (int j = 0; j < 16; j++) {
        int f = tid + j * 256;
        int row = f >> 5, c4 = f & 31;
        int r = p0 + row;
        float4 v = (r < NPTS) ? *(const float4*)&x[r * CDIM + c4 * 4]
                              : make_float4(0.f, 0.f, 0.f, 0.f);
        *(uint4*)&s_x[row * GXSTR + c4 * 4] = tf32x4(v);
    }
    uint4 wv[4];
#pragma unroll
    for (int j = 0; j < 4; j++) wv[j] = tf32x4(((const float4*)w1)[tid + j * 256]);

    float acc[2][8][4];
#pragma unroll
    for (int mt = 0; mt < 2; mt++)
#pragma unroll
        for (int nt = 0; nt < 8; nt++)
#pragma unroll
            for (int i = 0; i < 4; i++) acc[mt][nt][i] = 0.f;

    for (int ch = 0; ch < 4; ch++) {
        const int b = ch & 1;
#pragma unroll
        for (int j = 0; j < 4; j++) {
            int f = tid + j * 256;
            *(uint4*)&s_wb[b][(f >> 5) * GWSTR + (f & 31) * 4] = wv[j];
        }
        __syncthreads();
        if (ch < 3) {
            const float4* ws = (const float4*)&w1[(ch + 1) * 32 * CDIM];
#pragma unroll
            for (int j = 0; j < 4; j++) wv[j] = tf32x4(ws[tid + j * 256]);
        }
        const uint32_t* ga = s_x + (mw * 32 + g) * GXSTR + ch * 32 + tg;
        const uint32_t* wb = s_wb[b] + tg * GWSTR + nw * 64 + g;
#pragma unroll
        for (int kk = 0; kk < 4; kk++) {
            const int co = kk * 8;
            uint32_t a[2][4];
#pragma unroll
            for (int mt = 0; mt < 2; mt++) {
                const uint32_t* gr = ga + mt * 16 * GXSTR + co;
                a[mt][0] = gr[0];
                a[mt][1] = gr[8 * GXSTR];
                a[mt][2] = gr[4];
                a[mt][3] = gr[8 * GXSTR + 4];
            }
            uint32_t bf[8][2];
#pragma unroll
            for (int nt = 0; nt < 8; nt++) {
                const uint32_t* wr = wb + co * GWSTR + nt * 8;
                bf[nt][0] = wr[0];
                bf[nt][1] = wr[4 * GWSTR];
            }
#pragma unroll
            for (int mt = 0; mt < 2; mt++)
#pragma unroll
                for (int nt = 0; nt < 8; nt++)
                    mma_tf32(acc[mt][nt], a[mt], bf[nt]);
        }
        __syncthreads();
    }

#pragma unroll
    for (int mt = 0; mt < 2; mt++) {
#pragma unroll
        for (int h = 0; h < 2; h++) {
            int row = p0 + mw * 32 + mt * 16 + g + h * 8;
            if (row < NPTS) {
#pragma unroll
                for (int nt = 0; nt < 8; nt++) {
                    int d = nw * 64 + nt * 8 + 2 * tg;
                    float2 bb = *(const float2*)&b1[d];
                    float2 o;
                    o.x = acc[mt][nt][h * 2 + 0] + bb.x;
                    o.y = acc[mt][nt][h * 2 + 1] + bb.y;
                    if (nw == 0)
                        *(float2*)&g_convx[row * HDIM + d] = o;
                    else
                        *(float2*)&g_trans[row * HDIM + d - HDIM] = o;
                }
            }
        }
    }
}

// ---------------------------------------------------------------------------
// K2/K3: sconv3 + ReLU, mma.sync tf32 (raw f32 operands), 3-stage cp.async
// G ring (XOR swizzle, no padding) + single-buffer W, 2 barriers/iter.
// ---------------------------------------------------------------------------
__global__ __launch_bounds__(256, 2) void sconv_mma_kernel(const float* __restrict__ feat,
                                                           float* __restrict__ outp,
                                                           const float* __restrict__ rw,
                                                           const float* __restrict__ rb,
                                                           const int* __restrict__ nbr)
{
    extern __shared__ char sm[];
    const uint32_t smb = smem_u32(sm);
    uint32_t* s_w = (uint32_t*)(sm + MM_W_OFF);

    const int tid  = threadIdx.x;
    const int wid  = tid >> 5;
    const int lane = tid & 31;
    const int mw   = wid >> 1;
    const int nw   = wid & 1;
    const int g    = lane >> 2;
    const int tg   = lane & 3;
    const int p0   = blockIdx.x * TP;

    // --- gather role: 2 threads per point, each 128B half ---
    const int pl = tid >> 1;
    const int hf = tid & 1;
    const int pt_g = p0 + pl;
    const bool pt_ok = (pt_g < NPTS);
    const uint32_t gx = (uint32_t)((pl & 7) << 2);   // G swizzle (word bits 2-4)

    // --- W staging: 4 x 16B per thread, swizzled [c][d ^ ((c&3)<<3)] ---
    uint32_t wsts[4];
    const float* wsrc[4];
#pragma unroll
    for (int j = 0; j < 4; j++) {
        int f = tid + j * 256;
        int row = f >> 4, col4 = (f & 15) * 4;
        wsts[j] = (uint32_t)(row * 64 + (col4 ^ ((row & 3) << 3)));
        wsrc[j] = rw + f * 4;
    }

    auto issueG = [&](int k, int idx) {
        uint32_t stage = smb + (uint32_t)((k % 3) * MM_GSTAGE);
        const float* s = (idx >= 0) ? (feat + (long)idx * HDIM + hf * 32)
                                    : (g_zero + hf * 32);
#pragma unroll
        for (int j = 0; j < 8; j++) {
            uint32_t w = (uint32_t)pl * 64u + (((uint32_t)(hf * 32 + j * 4)) ^ gx);
            cp16(stage + w * 4u, s + j * 4);
        }
    };

    // prologue: G groups for k=0,1 in flight; W_0 in regs; idx for k=2 ready
    int idx_n;
    {
        int idx0 = pt_ok ? nbr[pt_g] : -1;
        int idx1 = pt_ok ? nbr[NPTS + pt_g] : -1;
        issueG(0, idx0); CP_COMMIT();
        issueG(1, idx1); CP_COMMIT();
        idx_n = pt_ok ? nbr[2 * NPTS + pt_g] : -1;
    }
    float4 wreg[4];
#pragma unroll
    for (int j = 0; j < 4; j++) wreg[j] = *(const float4*)(wsrc[j]);

    float acc[2][4][4];
#pragma unroll
    for (int mt = 0; mt < 2; mt++)
#pragma unroll
        for (int nt = 0; nt < 4; nt++)
#pragma unroll
            for (int i = 0; i < 4; i++) acc[mt][nt][i] = 0.f;

    for (int k = 0; k < NK; k++) {
        // issue G for k+2 into the stage freed at last barB
        if (k + 2 < NK) { issueG(k + 2, idx_n); CP_COMMIT(); }
        // stage W_k (raw f32 bits; W buf free since last barB)
#pragma unroll
        for (int j = 0; j < 4; j++) {
            uint4 u = *(const uint4*)&wreg[j];
            *(uint4*)&s_w[wsts[j]] = u;
        }
        // ensure G group k landed
        if (k + 2 < NK)      CP_WAIT(2);
        else if (k + 1 < NK) CP_WAIT(1);
        else                 CP_WAIT(0);
        __syncthreads();                       // barA: G_k + W_k visible

        // prefetch W_{k+1} and idx for k+3 (overlaps compute)
        if (k + 1 < NK) {
            const float* wsk = rw + (k + 1) * HDIM * HDIM;
#pragma unroll
            for (int j = 0; j < 4; j++) wreg[j] = *(const float4*)((const char*)wsrc[j] + (size_t)(k + 1) * HDIM * HDIM * 4);
            (void)wsk;
        }
        idx_n = (pt_ok && k + 3 < NK) ? nbr[(k + 3) * NPTS + pt_g] : -1;

        // compute: 8 K-steps of m16n8k8 from stage k%3 + W buf
        const uint32_t* sg = (const uint32_t*)(sm + (k % 3) * MM_GSTAGE);
        const int r0 = mw * 32 + g;
#pragma unroll
        for (int kk = 0; kk < 8; kk++) {
            const int co = kk * 8;
            const int ac0 = (int)(((uint32_t)(co + tg)) ^ (uint32_t)(g << 2));
            const int ac1 = (int)(((uint32_t)(co + tg + 4)) ^ (uint32_t)(g << 2));
            uint32_t a[2][4];
#pragma unroll
            for (int mt = 0; mt < 2; mt++) {
                const int rr = (r0 + mt * 16) * 64;
                a[mt][0] = sg[rr + ac0];
                a[mt][1] = sg[rr + 8 * 64 + ac0];
                a[mt][2] = sg[rr + ac1];
                a[mt][3] = sg[rr + 8 * 64 + ac1];
            }
            uint32_t bf[4][4];
            const int br0 = (co + tg) * 64;
#pragma unroll
            for (int nt = 0; nt < 4; nt++) {
                const int bc = (int)(((uint32_t)(nw * 32 + nt * 8 + g)) ^ (uint32_t)(tg << 3));
                bf[nt][0] = s_w[br0 + bc];
                bf[nt][1] = s_w[br0 + 4 * 64 + bc];
            }
#pragma unroll
            for (int mt = 0; mt < 2; mt++)
#pragma unroll
                for (int nt = 0; nt < 4; nt++)
                    mma_tf32(acc[mt][nt], a[mt], bf[nt]);
        }
        __syncthreads();                       // barB: release stage k%3 + W buf
    }

    // epilogue: bias + ReLU + store
#pragma unroll
    for (int mt = 0; mt < 2; mt++) {
#pragma unroll
        for (int half = 0; half < 2; half++) {
            int pt = p0 + mw * 32 + mt * 16 + g + half * 8;
            if (pt < NPTS) {
                float* orow = outp + (long)pt * HDIM;
#pragma unroll
                for (int nt = 0; nt < 4; nt++) {
                    int d = nw * 32 + nt * 8 + 2 * tg;
                    float2 bb = *(const float2*)&rb[d];
                    float2 o;
                    o.x = fmaxf(acc[mt][nt][half * 2 + 0] + bb.x, 0.f);
                    o.y = fmaxf(acc[mt][nt][half * 2 + 1] + bb.y, 0.f);
                    *(float2*)&orow[d] = o;
                }
            }
        }
    }
}

// ---------------------------------------------------------------------------
// K4: out = x + concat(g_r2 + 2*g_convx, g_trans) @ w2 + b2.  tf32 mma.
// ---------------------------------------------------------------------------
__global__ __launch_bounds__(256, 2) void gemm2_kernel(const float* __restrict__ x,
                                                       const float* __restrict__ w2,
                                                       const float* __restrict__ b2,
                                                       float* __restrict__ out)
{
    extern __shared__ char sm[];
    uint32_t* s_x = (uint32_t*)(sm + GX_OFF);
    uint32_t* s_wb[2] = { (uint32_t*)(sm + GW_OFF), (uint32_t*)(sm + GW_OFF + GW_BUF) };

    const int tid  = threadIdx.x;
    const int wid  = tid >> 5;
    const int lane = tid & 31;
    const int mw   = wid >> 1;
    const int nw   = wid & 1;
    const int g    = lane >> 2;
    const int tg   = lane & 3;
    const int p0   = blockIdx.x * GP;

#pragma unroll
    for (int j = 0; j < 16; j++) {
        int f = tid + j * 256;
        int row = f >> 5, c4 = f & 31;
        int r = p0 + row;
        float4 v = make_float4(0.f, 0.f, 0.f, 0.f);
        if (r < NPTS) {
            if (c4 < 16) {
                float4 a = *(const float4*)&g_r2[r * HDIM + c4 * 4];
                float4 b = *(const float4*)&g_convx[r * HDIM + c4 * 4];
                v = make_float4(fmaf(2.f, b.x, a.x), fmaf(2.f, b.y, a.y),
                                fmaf(2.f, b.z, a.z), fmaf(2.f, b.w, a.w));
            } else {
                v = *(const float4*)&g_trans[r * HDIM + (c4 - 16) * 4];
            }
        }
        *(uint4*)&s_x[row * GXSTR + c4 * 4] = tf32x4(v);
    }
    uint4 wv[4];
#pragma unroll
    for (int j = 0; j < 4; j++) wv[j] = tf32x4(((const float4*)w2)[tid + j * 256]);

    float acc[2][8][4];
#pragma unroll
    for (int mt = 0; mt < 2; mt++)
#pragma unroll
        for (int nt = 0; nt < 8; nt++)
#pragma unroll
            for (int i = 0; i < 4; i++) acc[mt][nt][i] = 0.f;

    for (int ch = 0; ch < 4; ch++) {
        const int b = ch & 1;
#pragma unroll
        for (int j = 0; j < 4; j++) {
            int f = tid + j * 256;
            *(uint4*)&s_wb[b][(f >> 5) * GWSTR + (f & 31) * 4] = wv[j];
        }
        __syncthreads();
        if (ch < 3) {
            const float4* ws = (const float4*)&w2[(ch + 1) * 32 * CDIM];
#pragma unroll
            for (int j = 0; j < 4; j++) wv[j] = tf32x4(ws[tid + j * 256]);
        }
        const uint32_t* ga = s_x + (mw * 32 + g) * GXSTR + ch * 32 + tg;
        const uint32_t* wb = s_wb[b] + tg * GWSTR + nw * 64 + g;
#pragma unroll
        for (int kk = 0; kk < 4; kk++) {
            const int co = kk * 8;
            uint32_t a[2][4];
#pragma unroll
            for (int mt = 0; mt < 2; mt++) {
                const uint32_t* gr = ga + mt * 16 * GXSTR + co;
                a[mt][0] = gr[0];
                a[mt][1] = gr[8 * GXSTR];
                a[mt][2] = gr[4];
                a[mt][3] = gr[8 * GXSTR + 4];
            }
            uint32_t bf[8][2];
#pragma unroll
            for (int nt = 0; nt < 8; nt++) {
                const uint32_t* wr = wb + co * GWSTR + nt * 8;
                bf[nt][0] = wr[0];
                bf[nt][1] = wr[4 * GWSTR];
            }
#pragma unroll
            for (int mt = 0; mt < 2; mt++)
#pragma unroll
                for (int nt = 0; nt < 8; nt++)
                    mma_tf32(acc[mt][nt], a[mt], bf[nt]);
        }
        __syncthreads();
    }

#pragma unroll
    for (int mt = 0; mt < 2; mt++) {
#pragma unroll
        for (int h = 0; h < 2; h++) {
            int row = p0 + mw * 32 + mt * 16 + g + h * 8;
            if (row < NPTS) {
#pragma unroll
                for (int nt = 0; nt < 8; nt++) {
                    int d = nw * 64 + nt * 8 + 2 * tg;
                    float2 bb = *(const float2*)&b2[d];
                    float2 xv = *(const float2*)&x[row * CDIM + d];
                    float2 o;
                    o.x = acc[mt][nt][h * 2 + 0] + bb.x + xv.x;
                    o.y = acc[mt][nt][h * 2 + 1] + bb.y + xv.y;
                    *(float2*)&out[row * CDIM + d] = o;
                }
            }
        }
    }
}

// ---------------------------------------------------------------------------
extern "C" void kernel_launch(void* const* d_in, const int* in_sizes, int n_in,
                              void* d_out, int out_size)
{
    const float* x   = (const float*)d_in[0];
    const float* w1  = (const float*)d_in[1];
    const float* b1  = (const float*)d_in[2];
    const float* w2  = (const float*)d_in[3];
    const float* b2  = (const float*)d_in[4];
    const float* rw1 = (const float*)d_in[5];
    const float* rb1 = (const float*)d_in[6];
    const float* rw2 = (const float*)d_in[7];
    const float* rb2 = (const float*)d_in[8];
    const int*   nbr = (const int*)d_in[9];
    float* out = (float*)d_out;

    float* p_convx; cudaGetSymbolAddress((void**)&p_convx, g_convx);
    float* p_r1;    cudaGetSymbolAddress((void**)&p_r1,    g_r1);
    float* p_r2;    cudaGetSymbolAddress((void**)&p_r2,    g_r2);
    float* p_zero;  cudaGetSymbolAddress((void**)&p_zero,  g_zero);

    cudaFuncSetAttribute(gemm1_kernel,     cudaFuncAttributeMaxDynamicSharedMemorySize, G_SMEM);
    cudaFuncSetAttribute(sconv_mma_kernel, cudaFuncAttributeMaxDynamicSharedMemorySize, MM_SMEM);
    cudaFuncSetAttribute(gemm2_kernel,     cudaFuncAttributeMaxDynamicSharedMemorySize, G_SMEM);

    cudaMemsetAsync(p_zero, 0, 64 * sizeof(float));
    gemm1_kernel<<<NT_GM, 256, G_SMEM>>>(x, w1, b1);
    sconv_mma_kernel<<<NT_MM, 256, MM_SMEM>>>(p_convx, p_r1, rw1, rb1, nbr);
    sconv_mma_kernel<<<NT_MM, 256, MM_SMEM>>>(p_r1,    p_r2, rw2, rb2, nbr);
    gemm2_kernel<<<NT_GM, 256, G_SMEM>>>(x, w2, b2, out);
}